// round 12
// baseline (speedup 1.0000x reference)
#include <cuda_runtime.h>
#include <cstdint>

#define ROWS_T   1048576
#define BINS     17
#define GROUPS   262144
#define TPB      128                // 4 warps -> all 4 SMSPs
#define GPB      64                 // groups per chunk (2 threads per group)
#define FPG      68
#define CHUNKS   (GROUPS / GPB)     // 4096
#define CONVN    33
#define SLAB     (GPB * FPG)        // 4352 floats per tensor
#define CHUNK_BYTES (SLAB * 4)      // 17408
#define SCRATCHN (GPB * CONVN)      // 2112 floats
#define GRID     760                // 152 SMs * 5 resident CTAs
#define SMEM_BYTES ((2 * SLAB + SCRATCHN) * 4)   // 43264

__device__ float2 g_part[GRID];
__device__ int    g_done = 0;

// ---- fast math ----
__device__ __forceinline__ float fast_ex2(float x) {
    float r; asm("ex2.approx.ftz.f32 %0, %1;" : "=f"(r) : "f"(x)); return r;
}
__device__ __forceinline__ float fast_lg2(float x) {
    float r; asm("lg2.approx.ftz.f32 %0, %1;" : "=f"(r) : "f"(x)); return r;
}
__device__ __forceinline__ float fast_rcp(float x) {
    float r; asm("rcp.approx.ftz.f32 %0, %1;" : "=f"(r) : "f"(x)); return r;
}
__device__ __forceinline__ unsigned long long pack2(float lo, float hi) {
    unsigned long long r;
    asm("mov.b64 %0, {%1, %2};" : "=l"(r) : "f"(lo), "f"(hi)); return r;
}
__device__ __forceinline__ void unpack2(unsigned long long v, float& lo, float& hi) {
    asm("mov.b64 {%0, %1}, %2;" : "=f"(lo), "=f"(hi) : "l"(v));
}
__device__ __forceinline__ unsigned long long ffma2(unsigned long long a,
                                                    unsigned long long b,
                                                    unsigned long long c) {
    unsigned long long d;
    asm("fma.rn.f32x2 %0, %1, %2, %3;" : "=l"(d) : "l"(a), "l"(b), "l"(c));
    return d;
}

// ---- TMA / mbarrier ----
__device__ __forceinline__ uint32_t smem_u32(const void* p) {
    return (uint32_t)__cvta_generic_to_shared(p);
}
__device__ __forceinline__ void mbar_init(uint32_t a, uint32_t cnt) {
    asm volatile("mbarrier.init.shared.b64 [%0], %1;" :: "r"(a), "r"(cnt) : "memory");
}
__device__ __forceinline__ void mbar_expect_tx(uint32_t a, uint32_t bytes) {
    asm volatile("mbarrier.arrive.expect_tx.shared.b64 _, [%0], %1;"
                 :: "r"(a), "r"(bytes) : "memory");
}
__device__ __forceinline__ void bulk_g2s(uint32_t dst, const void* src,
                                         uint32_t bytes, uint32_t mbar) {
    asm volatile("cp.async.bulk.shared::cta.global.mbarrier::complete_tx::bytes "
                 "[%0], [%1], %2, [%3];"
                 :: "r"(dst), "l"(src), "r"(bytes), "r"(mbar) : "memory");
}
__device__ __forceinline__ void fence_proxy_async_shared() {
    asm volatile("fence.proxy.async.shared::cta;" ::: "memory");
}
__device__ __forceinline__ void mbar_wait(uint32_t mbar, uint32_t parity) {
    uint32_t done;
    asm volatile(
        "{\n\t.reg .pred p;\n\t"
        "mbarrier.try_wait.parity.acquire.cta.shared::cta.b64 p, [%1], %2;\n\t"
        "selp.b32 %0, 1, 0, p;\n\t}"
        : "=r"(done) : "r"(mbar), "r"(parity) : "memory");
    if (!done) {
        asm volatile(
            "{\n\t.reg .pred P1;\n\t"
            "WL_%=:\n\t"
            "mbarrier.try_wait.parity.acquire.cta.shared::cta.b64 P1, [%0], %1, 0x989680;\n\t"
            "@P1 bra.uni WD_%=;\n\t"
            "bra.uni WL_%=;\n\t"
            "WD_%=:\n\t}"
            :: "r"(mbar), "r"(parity) : "memory");
    }
}

#define LOG2E 1.4426950408889634f
#define LN2   0.6931471805599453f

// One row (registers). er[17] = exp(y_j) raw numerators, *invOut = 1/sum.
__device__ __forceinline__ float process_row(const float* __restrict__ x,
                                             const float* __restrict__ y,
                                             float* __restrict__ er,
                                             float* __restrict__ invOut) {
    float s0 = 0.f, s1 = 0.f, q0 = 0.f, q1 = 0.f;
#pragma unroll
    for (int j = 0; j < BINS; j += 2) { s0 += x[j]; q0 = fmaf(x[j], x[j], q0); }
#pragma unroll
    for (int j = 1; j < BINS; j += 2) { s1 += x[j]; q1 = fmaf(x[j], x[j], q1); }
    float mux = (s0 + s1) * (1.0f / 17.0f);
    float vx  = fmaf(-17.0f * mux, mux, q0 + q1) * (1.0f / 16.0f);
    float isx = 0.1f * fast_rcp(1e-7f + sqrtf(vx));
    float kx  = isx * LOG2E;
    float bx  = mux * kx;
    float e0 = 0.f, e1 = 0.f;
#pragma unroll
    for (int j = 0; j < BINS; j += 2) e0 += fast_ex2(fmaf(x[j], kx, -bx));
#pragma unroll
    for (int j = 1; j < BINS; j += 2) e1 += fast_ex2(fmaf(x[j], kx, -bx));
    float lses = LN2 * fast_lg2(e0 + e1);

    float u0 = 0.f, u1 = 0.f, r0 = 0.f, r1 = 0.f;
#pragma unroll
    for (int j = 0; j < BINS; j += 2) { u0 += y[j]; r0 = fmaf(y[j], y[j], r0); }
#pragma unroll
    for (int j = 1; j < BINS; j += 2) { u1 += y[j]; r1 = fmaf(y[j], y[j], r1); }
    float muy = (u0 + u1) * (1.0f / 17.0f);
    float vy  = fmaf(-17.0f * muy, muy, r0 + r1) * (1.0f / 16.0f);
    float isy = 0.1f * fast_rcp(1e-7f + sqrtf(vy));
    float ky  = isy * LOG2E;
    float by  = muy * ky;

    float Et = 0.f, E2 = 0.f, dx = 0.f, dy = 0.f;
#pragma unroll
    for (int j = 0; j < BINS; j++) {
        float e = fast_ex2(fmaf(y[j], ky, -by));
        Et += e;
        dx = fmaf(e, x[j], dx);
        dy = fmaf(e, y[j], dy);
        float r = fast_ex2(y[j] * LOG2E);
        E2 += r;
        er[j] = r;
    }
    *invOut = fast_rcp(E2);

    float invEt = fast_rcp(Et);
    float lset  = LN2 * fast_lg2(Et);

    return (dy * invEt - muy) * isy - lset
         - (dx * invEt - mux) * isx + lses;
}

__global__ __launch_bounds__(TPB, 5)
void kd_main(const char* __restrict__ pred_b,
             const char* __restrict__ soft_b,
             const float4* __restrict__ w4,
             float* __restrict__ out) {
    extern __shared__ float dyn[];     // sp[SLAB] | ss[SLAB] | scratch[SCRATCHN]
    __shared__ float  red[8];
    __shared__ double dred[8];
    __shared__ int    s_last;
    __shared__ __align__(8) unsigned long long mbar_store;

    const int tid = threadIdx.x;
    const uint32_t mb    = smem_u32(&mbar_store);
    const uint32_t sp_a  = smem_u32(dyn);
    const uint32_t ss_a  = sp_a + CHUNK_BYTES;

    float* sp = dyn;
    float* ss = dyn + SLAB;
    float* sc = dyn + 2 * SLAB;

    if (tid == 0) {
        mbar_init(mb, 1);
        fence_proxy_async_shared();
    }
    __syncthreads();

    int c = blockIdx.x;
    uint32_t par = 0;

    if (tid == 0) {                    // prologue: fetch first chunk
        mbar_expect_tx(mb, 2 * CHUNK_BYTES);
        bulk_g2s(sp_a, pred_b + (size_t)c * CHUNK_BYTES, CHUNK_BYTES, mb);
        bulk_g2s(ss_a, soft_b + (size_t)c * CHUNK_BYTES, CHUNK_BYTES, mb);
    }

    const int g   = tid >> 1;
    const int hh  = tid & 1;           // 0 -> rows 0,1 (tb); 1 -> rows 2,3 (lr)
    const int off = g * FPG + hh * 34;

    float kl_acc = 0.f, w_acc = 0.f;

    for (; c < CHUNKS; c += GRID) {
        mbar_wait(mb, par); par ^= 1;

        // ---- slab -> registers (float2), then slabs are dead ----
        float bx[34], by[34];
        {
            const float2* p2 = reinterpret_cast<const float2*>(sp + off);
            const float2* q2 = reinterpret_cast<const float2*>(ss + off);
#pragma unroll
            for (int m = 0; m < 17; m++) {
                float2 a = p2[m]; bx[2 * m] = a.x; bx[2 * m + 1] = a.y;
                float2 b = q2[m]; by[2 * m] = b.x; by[2 * m + 1] = b.y;
            }
        }
        __syncthreads();               // all slab reads + prev out-store done

        // ---- prefetch next chunk into the SAME buffers (overlaps compute) ----
        const int cn = c + GRID;
        if (tid == 0 && cn < CHUNKS) {
            fence_proxy_async_shared();
            mbar_expect_tx(mb, 2 * CHUNK_BYTES);
            bulk_g2s(sp_a, pred_b + (size_t)cn * CHUNK_BYTES, CHUNK_BYTES, mb);
            bulk_g2s(ss_a, soft_b + (size_t)cn * CHUNK_BYTES, CHUNK_BYTES, mb);
        }

        float t0[BINS], t1[BINS];
        float inv0, inv1;
        kl_acc += process_row(bx,      by,      t0, &inv0);
        kl_acc += process_row(bx + 17, by + 17, t1, &inv1);

        // ---- packed f32x2 full convolution (normalizers folded) ----
        const float cc = inv0 * inv1;
        unsigned long long t1p[9], t1s[9], P[17];
#pragma unroll
        for (int q = 0; q < 17; q++) P[q] = 0ULL;
#pragma unroll
        for (int m = 0; m < 8; m++) t1p[m] = pack2(t1[2 * m], t1[2 * m + 1]);
        t1p[8] = pack2(t1[16], 0.f);
        t1s[0] = pack2(0.f, t1[0]);
#pragma unroll
        for (int m = 1; m < 9; m++) t1s[m] = pack2(t1[2 * m - 1], t1[2 * m]);

#pragma unroll
        for (int ie = 0; ie < 9; ie++) {
            float a = t0[2 * ie] * cc;
            unsigned long long A = pack2(a, a);
#pragma unroll
            for (int m = 0; m < 9; m++) P[ie + m] = ffma2(A, t1p[m], P[ie + m]);
        }
#pragma unroll
        for (int io = 0; io < 8; io++) {
            float a = t0[2 * io + 1] * cc;
            unsigned long long A = pack2(a, a);
#pragma unroll
            for (int m = 0; m < 9; m++) P[io + m] = ffma2(A, t1s[m], P[io + m]);
        }

        float conv[CONVN];
#pragma unroll
        for (int q = 0; q < 17; q++) {
            float lo, hi;
            unpack2(P[q], lo, hi);
            conv[2 * q] = lo;
            if (2 * q + 1 < CONVN) conv[2 * q + 1] = hi;
        }

        // ---- weight (even lanes: 4 rows' weights per group) ----
        if (!hh) {
            float4 w = w4[(size_t)c * GPB + g];
            w_acc += (w.x + w.y) + (w.z + w.w);
        }

        // ---- split ratio into scratch: even k=0..16, odd k=16..32 ----
#pragma unroll
        for (int m = 0; m < 17; m++) {
            float send = hh ? conv[m] : conv[m + 16];
            float v    = __shfl_xor_sync(0xffffffffu, send, 1);
            float num  = hh ? conv[m + 16] : v;
            float den  = (hh ? v : conv[m]) + 1e-8f;
            float rat  = num * fast_rcp(den);
            sc[g * CONVN + m + (hh ? 16 : 0)] = rat;
        }

        __syncthreads();               // scratch visible

        // ---- coalesced output: 2112 floats ----
        size_t obase = 1 + (size_t)c * (GPB * CONVN);
#pragma unroll
        for (int k = 0; k < 17; k++) {
            int i = tid + k * TPB;
            if (i < SCRATCHN) out[obase + i] = sc[i];
        }
    }

    // ---- one block reduction at exit ----
    float v0 = kl_acc, v1 = w_acc;
#pragma unroll
    for (int o = 16; o > 0; o >>= 1) {
        v0 += __shfl_down_sync(0xffffffffu, v0, o);
        v1 += __shfl_down_sync(0xffffffffu, v1, o);
    }
    if ((tid & 31) == 0) {
        red[(tid >> 5) * 2]     = v0;
        red[(tid >> 5) * 2 + 1] = v1;
    }
    __syncthreads();
    if (tid == 0) {
        g_part[blockIdx.x] = make_float2(red[0] + red[2] + red[4] + red[6],
                                         red[1] + red[3] + red[5] + red[7]);
        __threadfence();
        int d = atomicAdd(&g_done, 1);
        s_last = (d == GRID - 1);
    }
    __syncthreads();

    // ---- last block: scalar loss over 760 block partials ----
    if (s_last) {
        __threadfence();
        double s0 = 0.0, s1 = 0.0;
        for (int i = tid; i < GRID; i += TPB) {
            float2 p = g_part[i];
            s0 += (double)p.x; s1 += (double)p.y;
        }
#pragma unroll
        for (int o = 16; o > 0; o >>= 1) {
            s0 += __shfl_down_sync(0xffffffffu, s0, o);
            s1 += __shfl_down_sync(0xffffffffu, s1, o);
        }
        if ((tid & 31) == 0) {
            dred[(tid >> 5) * 2]     = s0;
            dred[(tid >> 5) * 2 + 1] = s1;
        }
        __syncthreads();
        if (tid == 0) {
            double S0 = dred[0] + dred[2] + dred[4] + dred[6];
            double S1 = dred[1] + dred[3] + dred[5] + dred[7];
            out[0] = (float)((S0 / (double)ROWS_T) * 100.0 * (S1 / (double)ROWS_T));
            g_done = 0;    // reset for next graph replay
        }
    }
}

extern "C" void kernel_launch(void* const* d_in, const int* in_sizes, int n_in,
                              void* d_out, int out_size) {
    const char* pred  = (const char*)d_in[0];
    const char* soft  = (const char*)d_in[1];
    const float4* w   = (const float4*)d_in[2];
    float* out = (float*)d_out;

    static int attr_set = 0;
    if (!attr_set) {
        cudaFuncSetAttribute(kd_main, cudaFuncAttributeMaxDynamicSharedMemorySize,
                             SMEM_BYTES);
        attr_set = 1;
    }
    kd_main<<<GRID, TPB, SMEM_BYTES>>>(pred, soft, w, out);
}

// round 13
// speedup vs baseline: 1.0422x; 1.0422x over previous
#include <cuda_runtime.h>
#include <cstdint>

#define ROWS_T   1048576
#define BINS     17
#define GROUPS   262144
#define TPB      128                // 4 warps -> all 4 SMSPs
#define GPB      64                 // groups per chunk (2 threads per group)
#define FPG      68
#define CHUNKS   (GROUPS / GPB)     // 4096
#define CONVN    33
#define SLAB     (GPB * FPG)        // 4352 floats per tensor
#define CHUNK_BYTES (SLAB * 4)      // 17408
#define SCRATCHN (GPB * CONVN)      // 2112 floats
#define GRID     760                // 152 SMs * 5 resident CTAs
#define SMEM_BYTES ((2 * SLAB + SCRATCHN) * 4)   // 43264

__device__ float2 g_part[GRID];
__device__ int    g_done = 0;

// ---- fast math ----
__device__ __forceinline__ float fast_ex2(float x) {
    float r; asm("ex2.approx.ftz.f32 %0, %1;" : "=f"(r) : "f"(x)); return r;
}
__device__ __forceinline__ float fast_lg2(float x) {
    float r; asm("lg2.approx.ftz.f32 %0, %1;" : "=f"(r) : "f"(x)); return r;
}
__device__ __forceinline__ float fast_rcp(float x) {
    float r; asm("rcp.approx.ftz.f32 %0, %1;" : "=f"(r) : "f"(x)); return r;
}
__device__ __forceinline__ unsigned long long pack2(float lo, float hi) {
    unsigned long long r;
    asm("mov.b64 %0, {%1, %2};" : "=l"(r) : "f"(lo), "f"(hi)); return r;
}
__device__ __forceinline__ void unpack2(unsigned long long v, float& lo, float& hi) {
    asm("mov.b64 {%0, %1}, %2;" : "=f"(lo), "=f"(hi) : "l"(v));
}
__device__ __forceinline__ unsigned long long ffma2(unsigned long long a,
                                                    unsigned long long b,
                                                    unsigned long long c) {
    unsigned long long d;
    asm("fma.rn.f32x2 %0, %1, %2, %3;" : "=l"(d) : "l"(a), "l"(b), "l"(c));
    return d;
}

// ---- TMA / mbarrier ----
__device__ __forceinline__ uint32_t smem_u32(const void* p) {
    return (uint32_t)__cvta_generic_to_shared(p);
}
__device__ __forceinline__ void mbar_init(uint32_t a, uint32_t cnt) {
    asm volatile("mbarrier.init.shared.b64 [%0], %1;" :: "r"(a), "r"(cnt) : "memory");
}
__device__ __forceinline__ void mbar_expect_tx(uint32_t a, uint32_t bytes) {
    asm volatile("mbarrier.arrive.expect_tx.shared.b64 _, [%0], %1;"
                 :: "r"(a), "r"(bytes) : "memory");
}
__device__ __forceinline__ void bulk_g2s(uint32_t dst, const void* src,
                                         uint32_t bytes, uint32_t mbar) {
    asm volatile("cp.async.bulk.shared::cta.global.mbarrier::complete_tx::bytes "
                 "[%0], [%1], %2, [%3];"
                 :: "r"(dst), "l"(src), "r"(bytes), "r"(mbar) : "memory");
}
__device__ __forceinline__ void fence_proxy_async_shared() {
    asm volatile("fence.proxy.async.shared::cta;" ::: "memory");
}
__device__ __forceinline__ void mbar_wait(uint32_t mbar, uint32_t parity) {
    uint32_t done;
    asm volatile(
        "{\n\t.reg .pred p;\n\t"
        "mbarrier.try_wait.parity.acquire.cta.shared::cta.b64 p, [%1], %2;\n\t"
        "selp.b32 %0, 1, 0, p;\n\t}"
        : "=r"(done) : "r"(mbar), "r"(parity) : "memory");
    if (!done) {
        asm volatile(
            "{\n\t.reg .pred P1;\n\t"
            "WL_%=:\n\t"
            "mbarrier.try_wait.parity.acquire.cta.shared::cta.b64 P1, [%0], %1, 0x989680;\n\t"
            "@P1 bra.uni WD_%=;\n\t"
            "bra.uni WL_%=;\n\t"
            "WD_%=:\n\t}"
            :: "r"(mbar), "r"(parity) : "memory");
    }
}

#define LOG2E 1.4426950408889634f
#define LN2   0.6931471805599453f

// One row (registers). er[17] = exp(y_j) raw numerators, *invOut = 1/sum.
__device__ __forceinline__ float process_row(const float* __restrict__ x,
                                             const float* __restrict__ y,
                                             float* __restrict__ er,
                                             float* __restrict__ invOut) {
    float s0 = 0.f, s1 = 0.f, q0 = 0.f, q1 = 0.f;
#pragma unroll
    for (int j = 0; j < BINS; j += 2) { s0 += x[j]; q0 = fmaf(x[j], x[j], q0); }
#pragma unroll
    for (int j = 1; j < BINS; j += 2) { s1 += x[j]; q1 = fmaf(x[j], x[j], q1); }
    float mux = (s0 + s1) * (1.0f / 17.0f);
    float vx  = fmaf(-17.0f * mux, mux, q0 + q1) * (1.0f / 16.0f);
    float isx = 0.1f * fast_rcp(1e-7f + sqrtf(vx));
    float kx  = isx * LOG2E;
    float bx  = mux * kx;
    float e0 = 0.f, e1 = 0.f;
#pragma unroll
    for (int j = 0; j < BINS; j += 2) e0 += fast_ex2(fmaf(x[j], kx, -bx));
#pragma unroll
    for (int j = 1; j < BINS; j += 2) e1 += fast_ex2(fmaf(x[j], kx, -bx));
    float lses = LN2 * fast_lg2(e0 + e1);

    float u0 = 0.f, u1 = 0.f, r0 = 0.f, r1 = 0.f;
#pragma unroll
    for (int j = 0; j < BINS; j += 2) { u0 += y[j]; r0 = fmaf(y[j], y[j], r0); }
#pragma unroll
    for (int j = 1; j < BINS; j += 2) { u1 += y[j]; r1 = fmaf(y[j], y[j], r1); }
    float muy = (u0 + u1) * (1.0f / 17.0f);
    float vy  = fmaf(-17.0f * muy, muy, r0 + r1) * (1.0f / 16.0f);
    float isy = 0.1f * fast_rcp(1e-7f + sqrtf(vy));
    float ky  = isy * LOG2E;
    float by  = muy * ky;

    float Et = 0.f, E2 = 0.f, dx = 0.f, dy = 0.f;
#pragma unroll
    for (int j = 0; j < BINS; j++) {
        float e = fast_ex2(fmaf(y[j], ky, -by));
        Et += e;
        dx = fmaf(e, x[j], dx);
        dy = fmaf(e, y[j], dy);
        float r = fast_ex2(y[j] * LOG2E);
        E2 += r;
        er[j] = r;
    }
    *invOut = fast_rcp(E2);

    float invEt = fast_rcp(Et);
    float lset  = LN2 * fast_lg2(Et);

    return (dy * invEt - muy) * isy - lset
         - (dx * invEt - mux) * isx + lses;
}

__global__ __launch_bounds__(TPB, 5)
void kd_main(const char* __restrict__ pred_b,
             const char* __restrict__ soft_b,
             const float4* __restrict__ w4,
             float* __restrict__ out) {
    extern __shared__ float dyn[];     // sp[SLAB] | ss[SLAB] | scratch[SCRATCHN]
    __shared__ float  red[8];
    __shared__ double dred[8];
    __shared__ int    s_last;
    __shared__ __align__(8) unsigned long long mbar_store;

    const int tid = threadIdx.x;
    const uint32_t mb    = smem_u32(&mbar_store);
    const uint32_t sp_a  = smem_u32(dyn);
    const uint32_t ss_a  = sp_a + CHUNK_BYTES;

    float* sp = dyn;
    float* ss = dyn + SLAB;
    float* sc = dyn + 2 * SLAB;

    if (tid == 0) {
        mbar_init(mb, 1);
        fence_proxy_async_shared();
    }
    __syncthreads();

    int c = blockIdx.x;
    uint32_t par = 0;

    if (tid == 0) {                    // prologue: fetch first chunk
        mbar_expect_tx(mb, 2 * CHUNK_BYTES);
        bulk_g2s(sp_a, pred_b + (size_t)c * CHUNK_BYTES, CHUNK_BYTES, mb);
        bulk_g2s(ss_a, soft_b + (size_t)c * CHUNK_BYTES, CHUNK_BYTES, mb);
    }

    const int g   = tid >> 1;
    const int hh  = tid & 1;           // 0 -> rows 0,1 (tb); 1 -> rows 2,3 (lr)
    const int off = g * FPG + hh * 34;

    float kl_acc = 0.f, w_acc = 0.f;

    for (; c < CHUNKS; c += GRID) {
        mbar_wait(mb, par); par ^= 1;

        // ---- slab -> registers (float2), then slabs are dead ----
        float bx[34], by[34];
        {
            const float2* p2 = reinterpret_cast<const float2*>(sp + off);
            const float2* q2 = reinterpret_cast<const float2*>(ss + off);
#pragma unroll
            for (int m = 0; m < 17; m++) {
                float2 a = p2[m]; bx[2 * m] = a.x; bx[2 * m + 1] = a.y;
                float2 b = q2[m]; by[2 * m] = b.x; by[2 * m + 1] = b.y;
            }
        }
        __syncthreads();               // all slab reads + prev out-store done

        // ---- prefetch next chunk into the SAME buffers (overlaps compute) ----
        const int cn = c + GRID;
        if (tid == 0 && cn < CHUNKS) {
            fence_proxy_async_shared();
            mbar_expect_tx(mb, 2 * CHUNK_BYTES);
            bulk_g2s(sp_a, pred_b + (size_t)cn * CHUNK_BYTES, CHUNK_BYTES, mb);
            bulk_g2s(ss_a, soft_b + (size_t)cn * CHUNK_BYTES, CHUNK_BYTES, mb);
        }

        float t0[BINS], t1[BINS];
        float inv0, inv1;
        kl_acc += process_row(bx,      by,      t0, &inv0);
        kl_acc += process_row(bx + 17, by + 17, t1, &inv1);

        // ---- convolution: packed FFMA2 for even i, scalar FFMA for odd i.
        //      (no shifted-pair bank -> ~18 fewer live regs at the peak) ----
        const float cc = inv0 * inv1;
        unsigned long long t1p[9], P[17];
#pragma unroll
        for (int q = 0; q < 17; q++) P[q] = 0ULL;
#pragma unroll
        for (int m = 0; m < 8; m++) t1p[m] = pack2(t1[2 * m], t1[2 * m + 1]);
        t1p[8] = pack2(t1[16], 0.f);

#pragma unroll
        for (int ie = 0; ie < 9; ie++) {          // even i = 2*ie
            float a = t0[2 * ie] * cc;
            unsigned long long A = pack2(a, a);
#pragma unroll
            for (int m = 0; m < 9; m++) P[ie + m] = ffma2(A, t1p[m], P[ie + m]);
        }

        float conv[CONVN + 1];                    // +1: even pass writes k=33 (zero lane)
#pragma unroll
        for (int q = 0; q < 17; q++)
            unpack2(P[q], conv[2 * q], conv[2 * q + 1]);

#pragma unroll
        for (int io = 0; io < 8; io++) {          // odd i = 2*io+1, scalar
            float a = t0[2 * io + 1] * cc;
#pragma unroll
            for (int j = 0; j < BINS; j++)
                conv[2 * io + 1 + j] = fmaf(a, t1[j], conv[2 * io + 1 + j]);
        }

        // ---- weight (even lanes: 4 rows' weights per group) ----
        if (!hh) {
            float4 w = w4[(size_t)c * GPB + g];
            w_acc += (w.x + w.y) + (w.z + w.w);
        }

        // ---- split ratio into scratch: even k=0..16, odd k=16..32 ----
#pragma unroll
        for (int m = 0; m < 17; m++) {
            float send = hh ? conv[m] : conv[m + 16];
            float v    = __shfl_xor_sync(0xffffffffu, send, 1);
            float num  = hh ? conv[m + 16] : v;
            float den  = (hh ? v : conv[m]) + 1e-8f;
            float rat  = num * fast_rcp(den);
            sc[g * CONVN + m + (hh ? 16 : 0)] = rat;
        }

        __syncthreads();               // scratch visible

        // ---- coalesced output: 2112 floats ----
        size_t obase = 1 + (size_t)c * (GPB * CONVN);
#pragma unroll
        for (int k = 0; k < 17; k++) {
            int i = tid + k * TPB;
            if (i < SCRATCHN) out[obase + i] = sc[i];
        }
    }

    // ---- one block reduction at exit ----
    float v0 = kl_acc, v1 = w_acc;
#pragma unroll
    for (int o = 16; o > 0; o >>= 1) {
        v0 += __shfl_down_sync(0xffffffffu, v0, o);
        v1 += __shfl_down_sync(0xffffffffu, v1, o);
    }
    if ((tid & 31) == 0) {
        red[(tid >> 5) * 2]     = v0;
        red[(tid >> 5) * 2 + 1] = v1;
    }
    __syncthreads();
    if (tid == 0) {
        g_part[blockIdx.x] = make_float2(red[0] + red[2] + red[4] + red[6],
                                         red[1] + red[3] + red[5] + red[7]);
        __threadfence();
        int d = atomicAdd(&g_done, 1);
        s_last = (d == GRID - 1);
    }
    __syncthreads();

    // ---- last block: scalar loss over 760 block partials ----
    if (s_last) {
        __threadfence();
        double s0 = 0.0, s1 = 0.0;
        for (int i = tid; i < GRID; i += TPB) {
            float2 p = g_part[i];
            s0 += (double)p.x; s1 += (double)p.y;
        }
#pragma unroll
        for (int o = 16; o > 0; o >>= 1) {
            s0 += __shfl_down_sync(0xffffffffu, s0, o);
            s1 += __shfl_down_sync(0xffffffffu, s1, o);
        }
        if ((tid & 31) == 0) {
            dred[(tid >> 5) * 2]     = s0;
            dred[(tid >> 5) * 2 + 1] = s1;
        }
        __syncthreads();
        if (tid == 0) {
            double S0 = dred[0] + dred[2] + dred[4] + dred[6];
            double S1 = dred[1] + dred[3] + dred[5] + dred[7];
            out[0] = (float)((S0 / (double)ROWS_T) * 100.0 * (S1 / (double)ROWS_T));
            g_done = 0;    // reset for next graph replay
        }
    }
}

extern "C" void kernel_launch(void* const* d_in, const int* in_sizes, int n_in,
                              void* d_out, int out_size) {
    const char* pred  = (const char*)d_in[0];
    const char* soft  = (const char*)d_in[1];
    const float4* w   = (const float4*)d_in[2];
    float* out = (float*)d_out;

    static int attr_set = 0;
    if (!attr_set) {
        cudaFuncSetAttribute(kd_main, cudaFuncAttributeMaxDynamicSharedMemorySize,
                             SMEM_BYTES);
        attr_set = 1;
    }
    kd_main<<<GRID, TPB, SMEM_BYTES>>>(pred, soft, w, out);
}